// round 13
// baseline (speedup 1.0000x reference)
#include <cuda_runtime.h>
#include <cuda_bf16.h>

// ============================================================================
// SO3onS2 — f32 inputs (element counts, insertion order re/im/cg), and
// f32 REAL-PART-ONLY output: out[b, col] = Re( sum_k T[..]*conj(f_l[k]) ),
// out_size = B*381 elements (4N bytes; matches the write-ceiling evidence).
//
// Per (l1,l2) pair (l1<=l2<=10), per batch b:
//   tp[j=m1*d2+m2] = f1[m1]*f2[m2]      (complex; f[-m] = (-1)^m conj(f[m]))
//   T[c] = sum_j tp[j]*CG[j,c]          (CG real; only c < used needed)
//   out[col(l)] = sum_k T[l^2-lmin^2+k]*conj(f_l[k]);  F-row(c) = lmin^2+c
//   used = (min(l1+l2,10)+1)^2-(l2-l1)^2   (54% of CG never read)
// ============================================================================

#define LMAXV 10
#define NPAIRS 66
#define BMAX 16384
#define NROWS 121
#define TPB 128
#define CT 32
#define JROWS 160
#define EGC 1824130LL

// SoA full-coefficient scratch: F[row][b]
__device__ float g_Fre[NROWS * BMAX];
__device__ float g_Fim[NROWS * BMAX];

struct PairTab {
    int l1[NPAIRS];
    int l2[NPAIRS];
    int cgoff[NPAIRS];
    int used[NPAIRS];
    int colbase[NPAIRS];
};

// ---------------------------------------------------------------------------
// Prep: full f coefficients into SoA f32 scratch.
// f[l][m>=0]=c[l,m]; f[l][m<0]=(-1)^{|m|}conj(c[l,|m|]); row = l*l+(m+l)
// ---------------------------------------------------------------------------
__global__ void prep_kernel(const float* __restrict__ cre,
                            const float* __restrict__ cim,
                            long long n_c, int B) {
    int b = blockIdx.x * blockDim.x + threadIdx.x;
    int r = blockIdx.y;
    if (b >= B || r >= NROWS) return;
    int l = (int)floorf(sqrtf((float)r + 0.5f));
    if (l > LMAXV) l = LMAXV;
    int m = r - l * l - l;
    int mm = (m >= 0) ? m : -m;
    long long idx = (long long)b * 121 + l * 11 + mm;
    float re = 0.f, im = 0.f;
    if (idx >= 0 && idx < n_c) {
        re = cre[idx];
        im = cim[idx];
    }
    if (m < 0) {
        float s = (mm & 1) ? -1.f : 1.f;
        re = s * re;
        im = -s * im;
    }
    g_Fre[r * B + b] = re;
    g_Fim[r * B + b] = im;
}

// ---------------------------------------------------------------------------
// Main body, templated on D2 = 2*l2+1 (f2 register-resident).
// Thread = one batch element; CG staged in smem (LDS.128 warp broadcast).
// ---------------------------------------------------------------------------
template <int D2>
__device__ __forceinline__ void pair_body(
    int l1, int cgoff, int used, int colbase,
    int b, int B, int ncols,
    const float* __restrict__ cg, long long cg_n,
    float* __restrict__ outf, long long out_n,
    float* cg_s)
{
    constexpr int L2V = (D2 - 1) / 2;
    constexpr int l2sq = L2V * L2V;
    const int d1 = 2 * l1 + 1;
    const int d  = d1 * D2;
    const int lmin  = L2V - l1;
    const int lmin2 = lmin * lmin;
    const int l1sq  = l1 * l1;

    float f2r[D2], f2i[D2];
#pragma unroll
    for (int m2 = 0; m2 < D2; ++m2) {
        int r = l2sq + m2;
        f2r[m2] = g_Fre[r * B + b];
        f2i[m2] = g_Fim[r * B + b];
    }

    constexpr int G1 = (JROWS / D2) > 0 ? (JROWS / D2) : 1;

    float sre = 0.f;
    int l = lmin;
    int nextb = (l + 1) * (l + 1) - lmin2;
    int out_col = colbase;

    for (int c0 = 0; c0 < used; c0 += CT) {
        float accR[CT], accI[CT];
#pragma unroll
        for (int i = 0; i < CT; ++i) { accR[i] = 0.f; accI[i] = 0.f; }

        for (int m1_0 = 0; m1_0 < d1; m1_0 += G1) {
            int g = (d1 - m1_0 < G1) ? (d1 - m1_0) : G1;
            int nfill = g * D2 * CT;
            if (nfill > JROWS * CT) nfill = JROWS * CT;
            __syncthreads();
            for (int idx = threadIdx.x; idx < nfill; idx += TPB) {
                int jr = idx >> 5;          // CT == 32
                int cc = idx & (CT - 1);
                int c  = c0 + cc;
                int j  = m1_0 * D2 + jr;
                long long gi = (long long)cgoff + (long long)j * d + c;
                float v = 0.f;
                if (c < used && gi >= 0 && gi < cg_n) v = cg[gi];
                cg_s[idx] = v;
            }
            __syncthreads();

            for (int mg = 0; mg < g; ++mg) {
                int r1 = l1sq + m1_0 + mg;
                float f1r = g_Fre[r1 * B + b];
                float f1i = g_Fim[r1 * B + b];
                const float* base = cg_s + mg * (D2 * CT);
#pragma unroll
                for (int m2 = 0; m2 < D2; ++m2) {
                    float tpr = f1r * f2r[m2] - f1i * f2i[m2];
                    float tpi = f1r * f2i[m2] + f1i * f2r[m2];
                    const float4* row = (const float4*)(base + m2 * CT);
#pragma unroll
                    for (int q = 0; q < CT / 4; ++q) {
                        float4 v = row[q];                 // LDS.128 broadcast
                        accR[4 * q + 0] += tpr * v.x;
                        accI[4 * q + 0] += tpi * v.x;
                        accR[4 * q + 1] += tpr * v.y;
                        accI[4 * q + 1] += tpi * v.y;
                        accR[4 * q + 2] += tpr * v.z;
                        accI[4 * q + 2] += tpi * v.z;
                        accR[4 * q + 3] += tpr * v.w;
                        accI[4 * q + 3] += tpi * v.w;
                    }
                }
            }
        }

        // Epilogue: Re( T * conj(f_l) ) accumulated per segment; row = lmin^2+c.
#pragma unroll
        for (int cc = 0; cc < CT; ++cc) {
            int c = c0 + cc;
            if (c < used) {
                float ar = accR[cc];
                float ai = accI[cc];
                int r = lmin2 + c;
                float flr = g_Fre[r * B + b];
                float fli = g_Fim[r * B + b];
                sre += ar * flr + ai * fli;   // Re(T * conj(fl))
                if (c + 1 == nextb) {
                    long long oi = (long long)b * ncols + out_col;
                    if (oi >= 0 && oi < out_n) outf[oi] = sre;   // f32 real
                    ++out_col;
                    sre = 0.f;
                    ++l;
                    nextb = (l + 1) * (l + 1) - lmin2;
                }
            }
        }
    }
}

__global__ __launch_bounds__(TPB)
void so3_main_kernel(PairTab tab, const float* __restrict__ cg, long long cg_n,
                     float* __restrict__ outf, long long out_n,
                     int B, int ncols) {
    __shared__ __align__(16) float cg_s[JROWS * CT];
    int p = blockIdx.y;
    if (p >= NPAIRS) return;
    int l1 = tab.l1[p];
    int l2 = tab.l2[p];
    int b = blockIdx.x * TPB + threadIdx.x;
    if (b >= B) b = B - 1;   // duplicate identical work; keeps syncs uniform

    int cgoff = tab.cgoff[p], used = tab.used[p], cb = tab.colbase[p];
    switch (l2) {
        case 0:  pair_body<1 >(l1, cgoff, used, cb, b, B, ncols, cg, cg_n, outf, out_n, cg_s); break;
        case 1:  pair_body<3 >(l1, cgoff, used, cb, b, B, ncols, cg, cg_n, outf, out_n, cg_s); break;
        case 2:  pair_body<5 >(l1, cgoff, used, cb, b, B, ncols, cg, cg_n, outf, out_n, cg_s); break;
        case 3:  pair_body<7 >(l1, cgoff, used, cb, b, B, ncols, cg, cg_n, outf, out_n, cg_s); break;
        case 4:  pair_body<9 >(l1, cgoff, used, cb, b, B, ncols, cg, cg_n, outf, out_n, cg_s); break;
        case 5:  pair_body<11>(l1, cgoff, used, cb, b, B, ncols, cg, cg_n, outf, out_n, cg_s); break;
        case 6:  pair_body<13>(l1, cgoff, used, cb, b, B, ncols, cg, cg_n, outf, out_n, cg_s); break;
        case 7:  pair_body<15>(l1, cgoff, used, cb, b, B, ncols, cg, cg_n, outf, out_n, cg_s); break;
        case 8:  pair_body<17>(l1, cgoff, used, cb, b, B, ncols, cg, cg_n, outf, out_n, cg_s); break;
        case 9:  pair_body<19>(l1, cgoff, used, cb, b, B, ncols, cg, cg_n, outf, out_n, cg_s); break;
        default: pair_body<21>(l1, cgoff, used, cb, b, B, ncols, cg, cg_n, outf, out_n, cg_s); break;
    }
}

// ---------------------------------------------------------------------------
static void build_tab(PairTab& tab, int* ncols_out) {
    int l1a[NPAIRS], l2a[NPAIRS], off[NPAIRS], usd[NPAIRS], cb[NPAIRS];
    long long cost[NPAIRS];
    int np = 0, col = 0;
    long long o = 0;
    for (int l1 = 0; l1 <= LMAXV; ++l1) {
        for (int l2 = l1; l2 <= LMAXV; ++l2) {
            int d1 = 2 * l1 + 1, d2 = 2 * l2 + 1, d = d1 * d2;
            int lmin = l2 - l1;
            int lcap = (l1 + l2 < LMAXV) ? (l1 + l2) : LMAXV;
            int u = (lcap + 1) * (lcap + 1) - lmin * lmin;
            l1a[np] = l1; l2a[np] = l2;
            off[np] = (int)o; usd[np] = u; cb[np] = col;
            cost[np] = (long long)d * u;
            o += (long long)d * d;
            col += (lcap - lmin + 1);
            ++np;
        }
    }
    bool taken[NPAIRS] = {false};
    for (int i = 0; i < NPAIRS; ++i) {          // heaviest pairs first
        int best = -1;
        for (int j = 0; j < NPAIRS; ++j)
            if (!taken[j] && (best < 0 || cost[j] > cost[best])) best = j;
        taken[best] = true;
        tab.l1[i] = l1a[best];
        tab.l2[i] = l2a[best];
        tab.cgoff[i] = off[best];
        tab.used[i] = usd[best];
        tab.colbase[i] = cb[best];
    }
    *ncols_out = col;   // 381
}

extern "C" void kernel_launch(void* const* d_in, const int* in_sizes, int n_in,
                              void* d_out, int out_size) {
    if (n_in < 3 || !d_out) return;

    // cg identified by its batch-independent element count.
    int icg = -1;
    for (int i = 0; i < n_in; ++i)
        if ((long long)in_sizes[i] == EGC) { icg = i; break; }
    if (icg < 0) icg = 2;   // default: insertion order (re, im, cg)

    // Coeff arrays: the equal-size pair among the rest (order-preserving).
    int ia = -1, ib = -1;
    for (int i = 0; i < n_in && ib < 0; ++i) {
        if (i == icg) continue;
        for (int j = i + 1; j < n_in; ++j) {
            if (j == icg) continue;
            if (in_sizes[i] == in_sizes[j]) { ia = i; ib = j; break; }
        }
    }
    if (ia < 0) {
        for (int i = 0; i < n_in; ++i) {
            if (i == icg) continue;
            if (ia < 0) ia = i;
            else { ib = i; break; }
        }
        if (ib < 0) return;
    }

    const float* cgp = (const float*)d_in[icg];
    const float *re, *im;
    // anchor first -> alphabetical listing (cg, im, re); else (re, im, cg)
    if (icg == 0) { im = (const float*)d_in[ia]; re = (const float*)d_in[ib]; }
    else          { re = (const float*)d_in[ia]; im = (const float*)d_in[ib]; }

    long long Sc = (in_sizes[ia] < in_sizes[ib]) ? in_sizes[ia] : in_sizes[ib];
    int B = (int)(Sc / 121);
    if (B < 1) return;
    if (B > BMAX) B = BMAX;
    long long n_c = (long long)B * 121;

    PairTab tab;
    int ncols;
    build_tab(tab, &ncols);

    // Output: f32 real part, N = B*ncols values (4N bytes — the write size
    // empirically proven safe by rounds 10-12).
    long long N = (long long)B * ncols;
    long long out_n = N;
    if ((long long)out_size >= N && (long long)out_size < 2 * N)
        out_n = (long long)out_size;   // exact element count if provided
    if (out_n > N) out_n = N;

    dim3 pg((unsigned)((B + 255) / 256), NROWS);
    prep_kernel<<<pg, 256>>>(re, im, n_c, B);

    dim3 mg((unsigned)((B + TPB - 1) / TPB), NPAIRS);
    so3_main_kernel<<<mg, TPB>>>(tab, cgp, EGC,
                                 (float*)d_out, out_n, B, ncols);
}

// round 14
// speedup vs baseline: 1.2650x; 1.2650x over previous
#include <cuda_runtime.h>
#include <cuda_bf16.h>

// ============================================================================
// SO3onS2 — f32 inputs (element counts), f32 REAL-PART-ONLY output
// (B*381 elements). PASSING ABI from R13; this round: packed f32x2 FMA.
//
// Per (l1,l2) pair (l1<=l2<=10), per batch b:
//   tp[j=m1*d2+m2] = f1[m1]*f2[m2]      (complex; f[-m] = (-1)^m conj(f[m]))
//   T[c] = sum_j tp[j]*CG[j,c]          (CG real; only c < used needed)
//   out[col(l)] = Re( sum_k T[l^2-lmin^2+k]*conj(f_l[k]) );  F-row(c)=lmin^2+c
//   used = (min(l1+l2,10)+1)^2-(l2-l1)^2   (54% of CG never read)
// ============================================================================

#define LMAXV 10
#define NPAIRS 66
#define BMAX 16384
#define NROWS 121
#define TPB 128
#define CT 32
#define JROWS 160
#define EGC 1824130LL

// SoA full-coefficient scratch: F[row][b]
__device__ float g_Fre[NROWS * BMAX];
__device__ float g_Fim[NROWS * BMAX];

struct PairTab {
    int l1[NPAIRS];
    int l2[NPAIRS];
    int cgoff[NPAIRS];
    int used[NPAIRS];
    int colbase[NPAIRS];
};

// ---------------------------------------------------------------------------
// Packed f32x2 helpers (sm_103a: fma.rn.f32x2 = 2x fp32 FMA throughput).
// All by-value (no references into register arrays).
// ---------------------------------------------------------------------------
__device__ __forceinline__ unsigned long long bcast2(float a) {
    unsigned long long r;
    asm("mov.b64 %0, {%1, %1};" : "=l"(r) : "f"(a));
    return r;
}
__device__ __forceinline__ unsigned long long fma2(unsigned long long a,
                                                   unsigned long long b,
                                                   unsigned long long c) {
    unsigned long long d;
    asm("fma.rn.f32x2 %0, %1, %2, %3;" : "=l"(d) : "l"(a), "l"(b), "l"(c));
    return d;
}
__device__ __forceinline__ float2 unpk2(unsigned long long v) {
    float2 r;
    asm("mov.b64 {%0, %1}, %2;" : "=f"(r.x), "=f"(r.y) : "l"(v));
    return r;
}

// ---------------------------------------------------------------------------
// Prep: full f coefficients into SoA f32 scratch.
// f[l][m>=0]=c[l,m]; f[l][m<0]=(-1)^{|m|}conj(c[l,|m|]); row = l*l+(m+l)
// ---------------------------------------------------------------------------
__global__ void prep_kernel(const float* __restrict__ cre,
                            const float* __restrict__ cim,
                            long long n_c, int B) {
    int b = blockIdx.x * blockDim.x + threadIdx.x;
    int r = blockIdx.y;
    if (b >= B || r >= NROWS) return;
    int l = (int)floorf(sqrtf((float)r + 0.5f));
    if (l > LMAXV) l = LMAXV;
    int m = r - l * l - l;
    int mm = (m >= 0) ? m : -m;
    long long idx = (long long)b * 121 + l * 11 + mm;
    float re = 0.f, im = 0.f;
    if (idx >= 0 && idx < n_c) {
        re = cre[idx];
        im = cim[idx];
    }
    if (m < 0) {
        float s = (mm & 1) ? -1.f : 1.f;
        re = s * re;
        im = -s * im;
    }
    g_Fre[r * B + b] = re;
    g_Fim[r * B + b] = im;
}

// ---------------------------------------------------------------------------
// Main body, templated on D2 = 2*l2+1 (f2 register-resident).
// Thread = one batch element; CG staged in smem (LDS.128 warp broadcast).
// Accumulators are packed f32x2 pairs of adjacent columns.
// ---------------------------------------------------------------------------
template <int D2>
__device__ __forceinline__ void pair_body(
    int l1, int cgoff, int used, int colbase,
    int b, int B, int ncols,
    const float* __restrict__ cg, long long cg_n,
    float* __restrict__ outf, long long out_n,
    float* cg_s)
{
    constexpr int L2V = (D2 - 1) / 2;
    constexpr int l2sq = L2V * L2V;
    const int d1 = 2 * l1 + 1;
    const int d  = d1 * D2;
    const int lmin  = L2V - l1;
    const int lmin2 = lmin * lmin;
    const int l1sq  = l1 * l1;

    float f2r[D2], f2i[D2];
#pragma unroll
    for (int m2 = 0; m2 < D2; ++m2) {
        int r = l2sq + m2;
        f2r[m2] = g_Fre[r * B + b];
        f2i[m2] = g_Fim[r * B + b];
    }

    constexpr int G1 = (JROWS / D2) > 0 ? (JROWS / D2) : 1;

    float sre = 0.f;
    int l = lmin;
    int nextb = (l + 1) * (l + 1) - lmin2;
    int out_col = colbase;

    for (int c0 = 0; c0 < used; c0 += CT) {
        unsigned long long accR[CT / 2], accI[CT / 2];
#pragma unroll
        for (int i = 0; i < CT / 2; ++i) { accR[i] = 0ull; accI[i] = 0ull; }

        for (int m1_0 = 0; m1_0 < d1; m1_0 += G1) {
            int g = (d1 - m1_0 < G1) ? (d1 - m1_0) : G1;
            int nfill = g * D2 * CT;
            if (nfill > JROWS * CT) nfill = JROWS * CT;
            __syncthreads();
            for (int idx = threadIdx.x; idx < nfill; idx += TPB) {
                int jr = idx >> 5;          // CT == 32
                int cc = idx & (CT - 1);
                int c  = c0 + cc;
                int j  = m1_0 * D2 + jr;
                long long gi = (long long)cgoff + (long long)j * d + c;
                float v = 0.f;
                if (c < used && gi >= 0 && gi < cg_n) v = cg[gi];
                cg_s[idx] = v;
            }
            __syncthreads();

            for (int mg = 0; mg < g; ++mg) {
                int r1 = l1sq + m1_0 + mg;
                float f1r = g_Fre[r1 * B + b];
                float f1i = g_Fim[r1 * B + b];
                const float* base = cg_s + mg * (D2 * CT);
#pragma unroll
                for (int m2 = 0; m2 < D2; ++m2) {
                    float tpr = f1r * f2r[m2] - f1i * f2i[m2];
                    float tpi = f1r * f2i[m2] + f1i * f2r[m2];
                    unsigned long long tpr2 = bcast2(tpr);
                    unsigned long long tpi2 = bcast2(tpi);
                    // 16B-aligned: base is 16B-aligned, m2*CT*4 = m2*128 B
                    const ulonglong2* row =
                        (const ulonglong2*)(base + m2 * CT);
#pragma unroll
                    for (int q = 0; q < CT / 4; ++q) {
                        ulonglong2 v = row[q];             // LDS.128 broadcast
                        accR[2 * q]     = fma2(tpr2, v.x, accR[2 * q]);
                        accI[2 * q]     = fma2(tpi2, v.x, accI[2 * q]);
                        accR[2 * q + 1] = fma2(tpr2, v.y, accR[2 * q + 1]);
                        accI[2 * q + 1] = fma2(tpi2, v.y, accI[2 * q + 1]);
                    }
                }
            }
        }

        // Epilogue: Re( T * conj(f_l) ) per running segment; F-row = lmin^2+c.
#pragma unroll
        for (int h = 0; h < CT / 2; ++h) {
            float2 vr = unpk2(accR[h]);
            float2 vi = unpk2(accI[h]);
#pragma unroll
            for (int t = 0; t < 2; ++t) {
                int c = c0 + 2 * h + t;
                if (c < used) {
                    float ar = (t == 0) ? vr.x : vr.y;
                    float ai = (t == 0) ? vi.x : vi.y;
                    int r = lmin2 + c;
                    float flr = g_Fre[r * B + b];
                    float fli = g_Fim[r * B + b];
                    sre += ar * flr + ai * fli;   // Re(T * conj(fl))
                    if (c + 1 == nextb) {
                        long long oi = (long long)b * ncols + out_col;
                        if (oi >= 0 && oi < out_n) outf[oi] = sre;
                        ++out_col;
                        sre = 0.f;
                        ++l;
                        nextb = (l + 1) * (l + 1) - lmin2;
                    }
                }
            }
        }
    }
}

__global__ __launch_bounds__(TPB)
void so3_main_kernel(PairTab tab, const float* __restrict__ cg, long long cg_n,
                     float* __restrict__ outf, long long out_n,
                     int B, int ncols) {
    __shared__ __align__(16) float cg_s[JROWS * CT];
    int p = blockIdx.y;
    if (p >= NPAIRS) return;
    int l1 = tab.l1[p];
    int l2 = tab.l2[p];
    int b = blockIdx.x * TPB + threadIdx.x;
    if (b >= B) b = B - 1;   // duplicate identical work; keeps syncs uniform

    int cgoff = tab.cgoff[p], used = tab.used[p], cb = tab.colbase[p];
    switch (l2) {
        case 0:  pair_body<1 >(l1, cgoff, used, cb, b, B, ncols, cg, cg_n, outf, out_n, cg_s); break;
        case 1:  pair_body<3 >(l1, cgoff, used, cb, b, B, ncols, cg, cg_n, outf, out_n, cg_s); break;
        case 2:  pair_body<5 >(l1, cgoff, used, cb, b, B, ncols, cg, cg_n, outf, out_n, cg_s); break;
        case 3:  pair_body<7 >(l1, cgoff, used, cb, b, B, ncols, cg, cg_n, outf, out_n, cg_s); break;
        case 4:  pair_body<9 >(l1, cgoff, used, cb, b, B, ncols, cg, cg_n, outf, out_n, cg_s); break;
        case 5:  pair_body<11>(l1, cgoff, used, cb, b, B, ncols, cg, cg_n, outf, out_n, cg_s); break;
        case 6:  pair_body<13>(l1, cgoff, used, cb, b, B, ncols, cg, cg_n, outf, out_n, cg_s); break;
        case 7:  pair_body<15>(l1, cgoff, used, cb, b, B, ncols, cg, cg_n, outf, out_n, cg_s); break;
        case 8:  pair_body<17>(l1, cgoff, used, cb, b, B, ncols, cg, cg_n, outf, out_n, cg_s); break;
        case 9:  pair_body<19>(l1, cgoff, used, cb, b, B, ncols, cg, cg_n, outf, out_n, cg_s); break;
        default: pair_body<21>(l1, cgoff, used, cb, b, B, ncols, cg, cg_n, outf, out_n, cg_s); break;
    }
}

// ---------------------------------------------------------------------------
static void build_tab(PairTab& tab, int* ncols_out) {
    int l1a[NPAIRS], l2a[NPAIRS], off[NPAIRS], usd[NPAIRS], cb[NPAIRS];
    long long cost[NPAIRS];
    int np = 0, col = 0;
    long long o = 0;
    for (int l1 = 0; l1 <= LMAXV; ++l1) {
        for (int l2 = l1; l2 <= LMAXV; ++l2) {
            int d1 = 2 * l1 + 1, d2 = 2 * l2 + 1, d = d1 * d2;
            int lmin = l2 - l1;
            int lcap = (l1 + l2 < LMAXV) ? (l1 + l2) : LMAXV;
            int u = (lcap + 1) * (lcap + 1) - lmin * lmin;
            l1a[np] = l1; l2a[np] = l2;
            off[np] = (int)o; usd[np] = u; cb[np] = col;
            cost[np] = (long long)d * u;
            o += (long long)d * d;
            col += (lcap - lmin + 1);
            ++np;
        }
    }
    bool taken[NPAIRS] = {false};
    for (int i = 0; i < NPAIRS; ++i) {          // heaviest pairs first
        int best = -1;
        for (int j = 0; j < NPAIRS; ++j)
            if (!taken[j] && (best < 0 || cost[j] > cost[best])) best = j;
        taken[best] = true;
        tab.l1[i] = l1a[best];
        tab.l2[i] = l2a[best];
        tab.cgoff[i] = off[best];
        tab.used[i] = usd[best];
        tab.colbase[i] = cb[best];
    }
    *ncols_out = col;   // 381
}

extern "C" void kernel_launch(void* const* d_in, const int* in_sizes, int n_in,
                              void* d_out, int out_size) {
    if (n_in < 3 || !d_out) return;

    // cg identified by its batch-independent element count.
    int icg = -1;
    for (int i = 0; i < n_in; ++i)
        if ((long long)in_sizes[i] == EGC) { icg = i; break; }
    if (icg < 0) icg = 2;   // default: insertion order (re, im, cg)

    // Coeff arrays: the equal-size pair among the rest (order-preserving).
    int ia = -1, ib = -1;
    for (int i = 0; i < n_in && ib < 0; ++i) {
        if (i == icg) continue;
        for (int j = i + 1; j < n_in; ++j) {
            if (j == icg) continue;
            if (in_sizes[i] == in_sizes[j]) { ia = i; ib = j; break; }
        }
    }
    if (ia < 0) {
        for (int i = 0; i < n_in; ++i) {
            if (i == icg) continue;
            if (ia < 0) ia = i;
            else { ib = i; break; }
        }
        if (ib < 0) return;
    }

    const float* cgp = (const float*)d_in[icg];
    const float *re, *im;
    // anchor first -> alphabetical listing (cg, im, re); else (re, im, cg)
    if (icg == 0) { im = (const float*)d_in[ia]; re = (const float*)d_in[ib]; }
    else          { re = (const float*)d_in[ia]; im = (const float*)d_in[ib]; }

    long long Sc = (in_sizes[ia] < in_sizes[ib]) ? in_sizes[ia] : in_sizes[ib];
    int B = (int)(Sc / 121);
    if (B < 1) return;
    if (B > BMAX) B = BMAX;
    long long n_c = (long long)B * 121;

    PairTab tab;
    int ncols;
    build_tab(tab, &ncols);

    // Output: f32 real part, N = B*ncols values.
    long long N = (long long)B * ncols;
    long long out_n = N;
    if ((long long)out_size >= N && (long long)out_size < 2 * N)
        out_n = (long long)out_size;
    if (out_n > N) out_n = N;

    dim3 pg((unsigned)((B + 255) / 256), NROWS);
    prep_kernel<<<pg, 256>>>(re, im, n_c, B);

    dim3 mg((unsigned)((B + TPB - 1) / TPB), NPAIRS);
    so3_main_kernel<<<mg, TPB>>>(tab, cgp, EGC,
                                 (float*)d_out, out_n, B, ncols);
}

// round 15
// speedup vs baseline: 1.6073x; 1.2706x over previous
#include <cuda_runtime.h>
#include <cuda_bf16.h>

// ============================================================================
// SO3onS2 — f32 inputs (element counts), f32 REAL-PART-ONLY output
// (B*381 elements). R14 engine (packed f32x2) + occupancy fixes:
// CT 32->16 (acc regs halved) and __launch_bounds__(128, 4).
//
// Per (l1,l2) pair (l1<=l2<=10), per batch b:
//   tp[j=m1*d2+m2] = f1[m1]*f2[m2]      (complex; f[-m] = (-1)^m conj(f[m]))
//   T[c] = sum_j tp[j]*CG[j,c]          (CG real; only c < used needed)
//   out[col(l)] = Re( sum_k T[l^2-lmin^2+k]*conj(f_l[k]) );  F-row(c)=lmin^2+c
//   used = (min(l1+l2,10)+1)^2-(l2-l1)^2   (54% of CG never read)
// ============================================================================

#define LMAXV 10
#define NPAIRS 66
#define BMAX 16384
#define NROWS 121
#define TPB 128
#define CT 16
#define JROWS 160
#define EGC 1824130LL

// SoA full-coefficient scratch: F[row][b]
__device__ float g_Fre[NROWS * BMAX];
__device__ float g_Fim[NROWS * BMAX];

struct PairTab {
    int l1[NPAIRS];
    int l2[NPAIRS];
    int cgoff[NPAIRS];
    int used[NPAIRS];
    int colbase[NPAIRS];
};

// ---------------------------------------------------------------------------
// Packed f32x2 helpers (sm_103a: fma.rn.f32x2 = 2x fp32 FMA throughput).
// ---------------------------------------------------------------------------
__device__ __forceinline__ unsigned long long bcast2(float a) {
    unsigned long long r;
    asm("mov.b64 %0, {%1, %1};" : "=l"(r) : "f"(a));
    return r;
}
__device__ __forceinline__ unsigned long long fma2(unsigned long long a,
                                                   unsigned long long b,
                                                   unsigned long long c) {
    unsigned long long d;
    asm("fma.rn.f32x2 %0, %1, %2, %3;" : "=l"(d) : "l"(a), "l"(b), "l"(c));
    return d;
}
__device__ __forceinline__ float2 unpk2(unsigned long long v) {
    float2 r;
    asm("mov.b64 {%0, %1}, %2;" : "=f"(r.x), "=f"(r.y) : "l"(v));
    return r;
}

// ---------------------------------------------------------------------------
// Prep: full f coefficients into SoA f32 scratch.
// f[l][m>=0]=c[l,m]; f[l][m<0]=(-1)^{|m|}conj(c[l,|m|]); row = l*l+(m+l)
// ---------------------------------------------------------------------------
__global__ void prep_kernel(const float* __restrict__ cre,
                            const float* __restrict__ cim,
                            long long n_c, int B) {
    int b = blockIdx.x * blockDim.x + threadIdx.x;
    int r = blockIdx.y;
    if (b >= B || r >= NROWS) return;
    int l = (int)floorf(sqrtf((float)r + 0.5f));
    if (l > LMAXV) l = LMAXV;
    int m = r - l * l - l;
    int mm = (m >= 0) ? m : -m;
    long long idx = (long long)b * 121 + l * 11 + mm;
    float re = 0.f, im = 0.f;
    if (idx >= 0 && idx < n_c) {
        re = cre[idx];
        im = cim[idx];
    }
    if (m < 0) {
        float s = (mm & 1) ? -1.f : 1.f;
        re = s * re;
        im = -s * im;
    }
    g_Fre[r * B + b] = re;
    g_Fim[r * B + b] = im;
}

// ---------------------------------------------------------------------------
// Main body, templated on D2 = 2*l2+1 (f2 register-resident).
// Thread = one batch element; CG staged in smem (LDS.128 warp broadcast).
// Accumulators: packed f32x2 pairs of adjacent columns (CT/2 u64 per R/I).
// ---------------------------------------------------------------------------
template <int D2>
__device__ __forceinline__ void pair_body(
    int l1, int cgoff, int used, int colbase,
    int b, int B, int ncols,
    const float* __restrict__ cg, long long cg_n,
    float* __restrict__ outf, long long out_n,
    float* cg_s)
{
    constexpr int L2V = (D2 - 1) / 2;
    constexpr int l2sq = L2V * L2V;
    const int d1 = 2 * l1 + 1;
    const int d  = d1 * D2;
    const int lmin  = L2V - l1;
    const int lmin2 = lmin * lmin;
    const int l1sq  = l1 * l1;

    float f2r[D2], f2i[D2];
#pragma unroll
    for (int m2 = 0; m2 < D2; ++m2) {
        int r = l2sq + m2;
        f2r[m2] = g_Fre[r * B + b];
        f2i[m2] = g_Fim[r * B + b];
    }

    constexpr int G1 = (JROWS / D2) > 0 ? (JROWS / D2) : 1;

    float sre = 0.f;
    int l = lmin;
    int nextb = (l + 1) * (l + 1) - lmin2;
    int out_col = colbase;

    for (int c0 = 0; c0 < used; c0 += CT) {
        unsigned long long accR[CT / 2], accI[CT / 2];
#pragma unroll
        for (int i = 0; i < CT / 2; ++i) { accR[i] = 0ull; accI[i] = 0ull; }

        for (int m1_0 = 0; m1_0 < d1; m1_0 += G1) {
            int g = (d1 - m1_0 < G1) ? (d1 - m1_0) : G1;
            int nfill = g * D2 * CT;
            if (nfill > JROWS * CT) nfill = JROWS * CT;
            __syncthreads();
            for (int idx = threadIdx.x; idx < nfill; idx += TPB) {
                int jr = idx / CT;
                int cc = idx & (CT - 1);
                int c  = c0 + cc;
                int j  = m1_0 * D2 + jr;
                long long gi = (long long)cgoff + (long long)j * d + c;
                float v = 0.f;
                if (c < used && gi >= 0 && gi < cg_n) v = cg[gi];
                cg_s[idx] = v;
            }
            __syncthreads();

            for (int mg = 0; mg < g; ++mg) {
                int r1 = l1sq + m1_0 + mg;
                float f1r = g_Fre[r1 * B + b];
                float f1i = g_Fim[r1 * B + b];
                const float* base = cg_s + mg * (D2 * CT);
#pragma unroll
                for (int m2 = 0; m2 < D2; ++m2) {
                    float tpr = f1r * f2r[m2] - f1i * f2i[m2];
                    float tpi = f1r * f2i[m2] + f1i * f2r[m2];
                    unsigned long long tpr2 = bcast2(tpr);
                    unsigned long long tpi2 = bcast2(tpi);
                    // 16B-aligned: base 16B-aligned, m2*CT*4 = m2*64 B
                    const ulonglong2* row =
                        (const ulonglong2*)(base + m2 * CT);
#pragma unroll
                    for (int q = 0; q < CT / 4; ++q) {
                        ulonglong2 v = row[q];             // LDS.128 broadcast
                        accR[2 * q]     = fma2(tpr2, v.x, accR[2 * q]);
                        accI[2 * q]     = fma2(tpi2, v.x, accI[2 * q]);
                        accR[2 * q + 1] = fma2(tpr2, v.y, accR[2 * q + 1]);
                        accI[2 * q + 1] = fma2(tpi2, v.y, accI[2 * q + 1]);
                    }
                }
            }
        }

        // Epilogue: Re( T * conj(f_l) ) per running segment; F-row = lmin^2+c.
#pragma unroll
        for (int h = 0; h < CT / 2; ++h) {
            float2 vr = unpk2(accR[h]);
            float2 vi = unpk2(accI[h]);
#pragma unroll
            for (int t = 0; t < 2; ++t) {
                int c = c0 + 2 * h + t;
                if (c < used) {
                    float ar = (t == 0) ? vr.x : vr.y;
                    float ai = (t == 0) ? vi.x : vi.y;
                    int r = lmin2 + c;
                    float flr = g_Fre[r * B + b];
                    float fli = g_Fim[r * B + b];
                    sre += ar * flr + ai * fli;   // Re(T * conj(fl))
                    if (c + 1 == nextb) {
                        long long oi = (long long)b * ncols + out_col;
                        if (oi >= 0 && oi < out_n) outf[oi] = sre;
                        ++out_col;
                        sre = 0.f;
                        ++l;
                        nextb = (l + 1) * (l + 1) - lmin2;
                    }
                }
            }
        }
    }
}

__global__ __launch_bounds__(TPB, 4)
void so3_main_kernel(PairTab tab, const float* __restrict__ cg, long long cg_n,
                     float* __restrict__ outf, long long out_n,
                     int B, int ncols) {
    __shared__ __align__(16) float cg_s[JROWS * CT];
    int p = blockIdx.y;
    if (p >= NPAIRS) return;
    int l1 = tab.l1[p];
    int l2 = tab.l2[p];
    int b = blockIdx.x * TPB + threadIdx.x;
    if (b >= B) b = B - 1;   // duplicate identical work; keeps syncs uniform

    int cgoff = tab.cgoff[p], used = tab.used[p], cb = tab.colbase[p];
    switch (l2) {
        case 0:  pair_body<1 >(l1, cgoff, used, cb, b, B, ncols, cg, cg_n, outf, out_n, cg_s); break;
        case 1:  pair_body<3 >(l1, cgoff, used, cb, b, B, ncols, cg, cg_n, outf, out_n, cg_s); break;
        case 2:  pair_body<5 >(l1, cgoff, used, cb, b, B, ncols, cg, cg_n, outf, out_n, cg_s); break;
        case 3:  pair_body<7 >(l1, cgoff, used, cb, b, B, ncols, cg, cg_n, outf, out_n, cg_s); break;
        case 4:  pair_body<9 >(l1, cgoff, used, cb, b, B, ncols, cg, cg_n, outf, out_n, cg_s); break;
        case 5:  pair_body<11>(l1, cgoff, used, cb, b, B, ncols, cg, cg_n, outf, out_n, cg_s); break;
        case 6:  pair_body<13>(l1, cgoff, used, cb, b, B, ncols, cg, cg_n, outf, out_n, cg_s); break;
        case 7:  pair_body<15>(l1, cgoff, used, cb, b, B, ncols, cg, cg_n, outf, out_n, cg_s); break;
        case 8:  pair_body<17>(l1, cgoff, used, cb, b, B, ncols, cg, cg_n, outf, out_n, cg_s); break;
        case 9:  pair_body<19>(l1, cgoff, used, cb, b, B, ncols, cg, cg_n, outf, out_n, cg_s); break;
        default: pair_body<21>(l1, cgoff, used, cb, b, B, ncols, cg, cg_n, outf, out_n, cg_s); break;
    }
}

// ---------------------------------------------------------------------------
static void build_tab(PairTab& tab, int* ncols_out) {
    int l1a[NPAIRS], l2a[NPAIRS], off[NPAIRS], usd[NPAIRS], cb[NPAIRS];
    long long cost[NPAIRS];
    int np = 0, col = 0;
    long long o = 0;
    for (int l1 = 0; l1 <= LMAXV; ++l1) {
        for (int l2 = l1; l2 <= LMAXV; ++l2) {
            int d1 = 2 * l1 + 1, d2 = 2 * l2 + 1, d = d1 * d2;
            int lmin = l2 - l1;
            int lcap = (l1 + l2 < LMAXV) ? (l1 + l2) : LMAXV;
            int u = (lcap + 1) * (lcap + 1) - lmin * lmin;
            l1a[np] = l1; l2a[np] = l2;
            off[np] = (int)o; usd[np] = u; cb[np] = col;
            cost[np] = (long long)d * u;
            o += (long long)d * d;
            col += (lcap - lmin + 1);
            ++np;
        }
    }
    bool taken[NPAIRS] = {false};
    for (int i = 0; i < NPAIRS; ++i) {          // heaviest pairs first
        int best = -1;
        for (int j = 0; j < NPAIRS; ++j)
            if (!taken[j] && (best < 0 || cost[j] > cost[best])) best = j;
        taken[best] = true;
        tab.l1[i] = l1a[best];
        tab.l2[i] = l2a[best];
        tab.cgoff[i] = off[best];
        tab.used[i] = usd[best];
        tab.colbase[i] = cb[best];
    }
    *ncols_out = col;   // 381
}

extern "C" void kernel_launch(void* const* d_in, const int* in_sizes, int n_in,
                              void* d_out, int out_size) {
    if (n_in < 3 || !d_out) return;

    // cg identified by its batch-independent element count.
    int icg = -1;
    for (int i = 0; i < n_in; ++i)
        if ((long long)in_sizes[i] == EGC) { icg = i; break; }
    if (icg < 0) icg = 2;   // default: insertion order (re, im, cg)

    // Coeff arrays: the equal-size pair among the rest (order-preserving).
    int ia = -1, ib = -1;
    for (int i = 0; i < n_in && ib < 0; ++i) {
        if (i == icg) continue;
        for (int j = i + 1; j < n_in; ++j) {
            if (j == icg) continue;
            if (in_sizes[i] == in_sizes[j]) { ia = i; ib = j; break; }
        }
    }
    if (ia < 0) {
        for (int i = 0; i < n_in; ++i) {
            if (i == icg) continue;
            if (ia < 0) ia = i;
            else { ib = i; break; }
        }
        if (ib < 0) return;
    }

    const float* cgp = (const float*)d_in[icg];
    const float *re, *im;
    // anchor first -> alphabetical listing (cg, im, re); else (re, im, cg)
    if (icg == 0) { im = (const float*)d_in[ia]; re = (const float*)d_in[ib]; }
    else          { re = (const float*)d_in[ia]; im = (const float*)d_in[ib]; }

    long long Sc = (in_sizes[ia] < in_sizes[ib]) ? in_sizes[ia] : in_sizes[ib];
    int B = (int)(Sc / 121);
    if (B < 1) return;
    if (B > BMAX) B = BMAX;
    long long n_c = (long long)B * 121;

    PairTab tab;
    int ncols;
    build_tab(tab, &ncols);

    // Output: f32 real part, N = B*ncols values.
    long long N = (long long)B * ncols;
    long long out_n = N;
    if ((long long)out_size >= N && (long long)out_size < 2 * N)
        out_n = (long long)out_size;
    if (out_n > N) out_n = N;

    dim3 pg((unsigned)((B + 255) / 256), NROWS);
    prep_kernel<<<pg, 256>>>(re, im, n_c, B);

    dim3 mg((unsigned)((B + TPB - 1) / TPB), NPAIRS);
    so3_main_kernel<<<mg, TPB>>>(tab, cgp, EGC,
                                 (float*)d_out, out_n, B, ncols);
}

// round 16
// speedup vs baseline: 1.7923x; 1.1151x over previous
#include <cuda_runtime.h>
#include <cuda_bf16.h>

// ============================================================================
// SO3onS2 — f32 inputs (element counts), f32 REAL-PART-ONLY output
// (B*381 elements). R15 engine + packed-complex tp (2 FMA2 vs 4 FMA) and
// JROWS 384 (fewer smem stages / barriers).
//
// Per (l1,l2) pair (l1<=l2<=10), per batch b:
//   tp[j=m1*d2+m2] = f1[m1]*f2[m2]      (complex; f[-m] = (-1)^m conj(f[m]))
//   T[c] = sum_j tp[j]*CG[j,c]          (CG real; only c < used needed)
//   out[col(l)] = Re( sum_k T[l^2-lmin^2+k]*conj(f_l[k]) );  F-row(c)=lmin^2+c
//   used = (min(l1+l2,10)+1)^2-(l2-l1)^2   (54% of CG never read)
// ============================================================================

#define LMAXV 10
#define NPAIRS 66
#define BMAX 16384
#define NROWS 121
#define TPB 128
#define CT 16
#define JROWS 384
#define EGC 1824130LL

// SoA full-coefficient scratch: F[row][b]
__device__ float g_Fre[NROWS * BMAX];
__device__ float g_Fim[NROWS * BMAX];

struct PairTab {
    int l1[NPAIRS];
    int l2[NPAIRS];
    int cgoff[NPAIRS];
    int used[NPAIRS];
    int colbase[NPAIRS];
};

// ---------------------------------------------------------------------------
// Packed f32x2 helpers (sm_103a: fma.rn.f32x2 = 2x fp32 FMA throughput).
// ---------------------------------------------------------------------------
__device__ __forceinline__ unsigned long long bcast2(float a) {
    unsigned long long r;
    asm("mov.b64 %0, {%1, %1};" : "=l"(r) : "f"(a));
    return r;
}
__device__ __forceinline__ unsigned long long pack2(float a, float b) {
    unsigned long long r;
    asm("mov.b64 %0, {%1, %2};" : "=l"(r) : "f"(a), "f"(b));
    return r;
}
__device__ __forceinline__ unsigned long long fma2(unsigned long long a,
                                                   unsigned long long b,
                                                   unsigned long long c) {
    unsigned long long d;
    asm("fma.rn.f32x2 %0, %1, %2, %3;" : "=l"(d) : "l"(a), "l"(b), "l"(c));
    return d;
}
__device__ __forceinline__ unsigned long long mul2(unsigned long long a,
                                                   unsigned long long b) {
    unsigned long long d;
    asm("mul.rn.f32x2 %0, %1, %2;" : "=l"(d) : "l"(a), "l"(b));
    return d;
}
__device__ __forceinline__ float2 unpk2(unsigned long long v) {
    float2 r;
    asm("mov.b64 {%0, %1}, %2;" : "=f"(r.x), "=f"(r.y) : "l"(v));
    return r;
}

// ---------------------------------------------------------------------------
// Prep: full f coefficients into SoA f32 scratch.
// f[l][m>=0]=c[l,m]; f[l][m<0]=(-1)^{|m|}conj(c[l,|m|]); row = l*l+(m+l)
// ---------------------------------------------------------------------------
__global__ void prep_kernel(const float* __restrict__ cre,
                            const float* __restrict__ cim,
                            long long n_c, int B) {
    int b = blockIdx.x * blockDim.x + threadIdx.x;
    int r = blockIdx.y;
    if (b >= B || r >= NROWS) return;
    int l = (int)floorf(sqrtf((float)r + 0.5f));
    if (l > LMAXV) l = LMAXV;
    int m = r - l * l - l;
    int mm = (m >= 0) ? m : -m;
    long long idx = (long long)b * 121 + l * 11 + mm;
    float re = 0.f, im = 0.f;
    if (idx >= 0 && idx < n_c) {
        re = cre[idx];
        im = cim[idx];
    }
    if (m < 0) {
        float s = (mm & 1) ? -1.f : 1.f;
        re = s * re;
        im = -s * im;
    }
    g_Fre[r * B + b] = re;
    g_Fim[r * B + b] = im;
}

// ---------------------------------------------------------------------------
// Main body, templated on D2 = 2*l2+1 (f2 register-resident).
// Thread = one batch element; CG staged in smem (LDS.128 warp broadcast).
// Accumulators: packed f32x2 pairs of adjacent columns. tp computed with
// packed complex multiply (2 FMA2).
// ---------------------------------------------------------------------------
template <int D2>
__device__ __forceinline__ void pair_body(
    int l1, int cgoff, int used, int colbase,
    int b, int B, int ncols,
    const float* __restrict__ cg, long long cg_n,
    float* __restrict__ outf, long long out_n,
    float* cg_s)
{
    constexpr int L2V = (D2 - 1) / 2;
    constexpr int l2sq = L2V * L2V;
    const int d1 = 2 * l1 + 1;
    const int d  = d1 * D2;
    const int lmin  = L2V - l1;
    const int lmin2 = lmin * lmin;
    const int l1sq  = l1 * l1;

    float f2r[D2], f2i[D2];
#pragma unroll
    for (int m2 = 0; m2 < D2; ++m2) {
        int r = l2sq + m2;
        f2r[m2] = g_Fre[r * B + b];
        f2i[m2] = g_Fim[r * B + b];
    }

    constexpr int G1 = (JROWS / D2) > 0 ? (JROWS / D2) : 1;

    float sre = 0.f;
    int l = lmin;
    int nextb = (l + 1) * (l + 1) - lmin2;
    int out_col = colbase;

    for (int c0 = 0; c0 < used; c0 += CT) {
        unsigned long long accR[CT / 2], accI[CT / 2];
#pragma unroll
        for (int i = 0; i < CT / 2; ++i) { accR[i] = 0ull; accI[i] = 0ull; }

        for (int m1_0 = 0; m1_0 < d1; m1_0 += G1) {
            int g = (d1 - m1_0 < G1) ? (d1 - m1_0) : G1;
            int nfill = g * D2 * CT;
            __syncthreads();
            // Unguarded fill: all indices provably < EGC for every pair
            // (used<=d, trailing pad lands in this or the next pair's block;
            // the last pair (10,10) has c_max=127 << d=441). Clamp = net.
            // Garbage in c>=used lanes is never read by the epilogue.
#pragma unroll 4
            for (int idx = threadIdx.x; idx < nfill; idx += TPB) {
                int jr = idx / CT;
                int cc = idx & (CT - 1);
                long long gi = (long long)cgoff +
                               (long long)(m1_0 * D2 + jr) * d + (c0 + cc);
                if (gi >= cg_n) gi = cg_n - 1;
                cg_s[idx] = cg[gi];
            }
            __syncthreads();

            for (int mg = 0; mg < g; ++mg) {
                int r1 = l1sq + m1_0 + mg;
                float f1r = g_Fre[r1 * B + b];
                float f1i = g_Fim[r1 * B + b];
                unsigned long long f1rr = bcast2(f1r);
                unsigned long long f1nm = pack2(-f1i, f1i);
                const float* base = cg_s + mg * (D2 * CT);
#pragma unroll
                for (int m2 = 0; m2 < D2; ++m2) {
                    // (tpr, tpi) = (f1r*f2r - f1i*f2i, f1r*f2i + f1i*f2r)
                    unsigned long long f2ri = pack2(f2r[m2], f2i[m2]);
                    unsigned long long f2ir = pack2(f2i[m2], f2r[m2]);
                    unsigned long long tp2 =
                        fma2(f1rr, f2ri, mul2(f1nm, f2ir));
                    float2 tp = unpk2(tp2);
                    unsigned long long tpr2 = bcast2(tp.x);
                    unsigned long long tpi2 = bcast2(tp.y);
                    const ulonglong2* row =
                        (const ulonglong2*)(base + m2 * CT);
#pragma unroll
                    for (int q = 0; q < CT / 4; ++q) {
                        ulonglong2 v = row[q];             // LDS.128 broadcast
                        accR[2 * q]     = fma2(tpr2, v.x, accR[2 * q]);
                        accI[2 * q]     = fma2(tpi2, v.x, accI[2 * q]);
                        accR[2 * q + 1] = fma2(tpr2, v.y, accR[2 * q + 1]);
                        accI[2 * q + 1] = fma2(tpi2, v.y, accI[2 * q + 1]);
                    }
                }
            }
        }

        // Epilogue: Re( T * conj(f_l) ) per running segment; F-row = lmin^2+c.
#pragma unroll
        for (int h = 0; h < CT / 2; ++h) {
            float2 vr = unpk2(accR[h]);
            float2 vi = unpk2(accI[h]);
#pragma unroll
            for (int t = 0; t < 2; ++t) {
                int c = c0 + 2 * h + t;
                if (c < used) {
                    float ar = (t == 0) ? vr.x : vr.y;
                    float ai = (t == 0) ? vi.x : vi.y;
                    int r = lmin2 + c;
                    float flr = g_Fre[r * B + b];
                    float fli = g_Fim[r * B + b];
                    sre += ar * flr + ai * fli;   // Re(T * conj(fl))
                    if (c + 1 == nextb) {
                        long long oi = (long long)b * ncols + out_col;
                        if (oi >= 0 && oi < out_n) outf[oi] = sre;
                        ++out_col;
                        sre = 0.f;
                        ++l;
                        nextb = (l + 1) * (l + 1) - lmin2;
                    }
                }
            }
        }
    }
}

__global__ __launch_bounds__(TPB, 4)
void so3_main_kernel(PairTab tab, const float* __restrict__ cg, long long cg_n,
                     float* __restrict__ outf, long long out_n,
                     int B, int ncols) {
    __shared__ __align__(16) float cg_s[JROWS * CT];
    int p = blockIdx.y;
    if (p >= NPAIRS) return;
    int l1 = tab.l1[p];
    int l2 = tab.l2[p];
    int b = blockIdx.x * TPB + threadIdx.x;
    if (b >= B) b = B - 1;   // duplicate identical work; keeps syncs uniform

    int cgoff = tab.cgoff[p], used = tab.used[p], cb = tab.colbase[p];
    switch (l2) {
        case 0:  pair_body<1 >(l1, cgoff, used, cb, b, B, ncols, cg, cg_n, outf, out_n, cg_s); break;
        case 1:  pair_body<3 >(l1, cgoff, used, cb, b, B, ncols, cg, cg_n, outf, out_n, cg_s); break;
        case 2:  pair_body<5 >(l1, cgoff, used, cb, b, B, ncols, cg, cg_n, outf, out_n, cg_s); break;
        case 3:  pair_body<7 >(l1, cgoff, used, cb, b, B, ncols, cg, cg_n, outf, out_n, cg_s); break;
        case 4:  pair_body<9 >(l1, cgoff, used, cb, b, B, ncols, cg, cg_n, outf, out_n, cg_s); break;
        case 5:  pair_body<11>(l1, cgoff, used, cb, b, B, ncols, cg, cg_n, outf, out_n, cg_s); break;
        case 6:  pair_body<13>(l1, cgoff, used, cb, b, B, ncols, cg, cg_n, outf, out_n, cg_s); break;
        case 7:  pair_body<15>(l1, cgoff, used, cb, b, B, ncols, cg, cg_n, outf, out_n, cg_s); break;
        case 8:  pair_body<17>(l1, cgoff, used, cb, b, B, ncols, cg, cg_n, outf, out_n, cg_s); break;
        case 9:  pair_body<19>(l1, cgoff, used, cb, b, B, ncols, cg, cg_n, outf, out_n, cg_s); break;
        default: pair_body<21>(l1, cgoff, used, cb, b, B, ncols, cg, cg_n, outf, out_n, cg_s); break;
    }
}

// ---------------------------------------------------------------------------
static void build_tab(PairTab& tab, int* ncols_out) {
    int l1a[NPAIRS], l2a[NPAIRS], off[NPAIRS], usd[NPAIRS], cb[NPAIRS];
    long long cost[NPAIRS];
    int np = 0, col = 0;
    long long o = 0;
    for (int l1 = 0; l1 <= LMAXV; ++l1) {
        for (int l2 = l1; l2 <= LMAXV; ++l2) {
            int d1 = 2 * l1 + 1, d2 = 2 * l2 + 1, d = d1 * d2;
            int lmin = l2 - l1;
            int lcap = (l1 + l2 < LMAXV) ? (l1 + l2) : LMAXV;
            int u = (lcap + 1) * (lcap + 1) - lmin * lmin;
            l1a[np] = l1; l2a[np] = l2;
            off[np] = (int)o; usd[np] = u; cb[np] = col;
            cost[np] = (long long)d * u;
            o += (long long)d * d;
            col += (lcap - lmin + 1);
            ++np;
        }
    }
    bool taken[NPAIRS] = {false};
    for (int i = 0; i < NPAIRS; ++i) {          // heaviest pairs first
        int best = -1;
        for (int j = 0; j < NPAIRS; ++j)
            if (!taken[j] && (best < 0 || cost[j] > cost[best])) best = j;
        taken[best] = true;
        tab.l1[i] = l1a[best];
        tab.l2[i] = l2a[best];
        tab.cgoff[i] = off[best];
        tab.used[i] = usd[best];
        tab.colbase[i] = cb[best];
    }
    *ncols_out = col;   // 381
}

extern "C" void kernel_launch(void* const* d_in, const int* in_sizes, int n_in,
                              void* d_out, int out_size) {
    if (n_in < 3 || !d_out) return;

    // cg identified by its batch-independent element count.
    int icg = -1;
    for (int i = 0; i < n_in; ++i)
        if ((long long)in_sizes[i] == EGC) { icg = i; break; }
    if (icg < 0) icg = 2;   // default: insertion order (re, im, cg)

    // Coeff arrays: the equal-size pair among the rest (order-preserving).
    int ia = -1, ib = -1;
    for (int i = 0; i < n_in && ib < 0; ++i) {
        if (i == icg) continue;
        for (int j = i + 1; j < n_in; ++j) {
            if (j == icg) continue;
            if (in_sizes[i] == in_sizes[j]) { ia = i; ib = j; break; }
        }
    }
    if (ia < 0) {
        for (int i = 0; i < n_in; ++i) {
            if (i == icg) continue;
            if (ia < 0) ia = i;
            else { ib = i; break; }
        }
        if (ib < 0) return;
    }

    const float* cgp = (const float*)d_in[icg];
    const float *re, *im;
    // anchor first -> alphabetical listing (cg, im, re); else (re, im, cg)
    if (icg == 0) { im = (const float*)d_in[ia]; re = (const float*)d_in[ib]; }
    else          { re = (const float*)d_in[ia]; im = (const float*)d_in[ib]; }

    long long Sc = (in_sizes[ia] < in_sizes[ib]) ? in_sizes[ia] : in_sizes[ib];
    int B = (int)(Sc / 121);
    if (B < 1) return;
    if (B > BMAX) B = BMAX;
    long long n_c = (long long)B * 121;

    PairTab tab;
    int ncols;
    build_tab(tab, &ncols);

    // Output: f32 real part, N = B*ncols values.
    long long N = (long long)B * ncols;
    long long out_n = N;
    if ((long long)out_size >= N && (long long)out_size < 2 * N)
        out_n = (long long)out_size;
    if (out_n > N) out_n = N;

    dim3 pg((unsigned)((B + 255) / 256), NROWS);
    prep_kernel<<<pg, 256>>>(re, im, n_c, B);

    dim3 mg((unsigned)((B + TPB - 1) / TPB), NPAIRS);
    so3_main_kernel<<<mg, TPB>>>(tab, cgp, EGC,
                                 (float*)d_out, out_n, B, ncols);
}